// round 1
// baseline (speedup 1.0000x reference)
#include <cuda_runtime.h>
#include <cuda_bf16.h>
#include <cstdint>

#define NPTS 2048
#define DIMS 96
#define NTHREADS 1024

// Device scratch (no runtime allocation allowed)
__device__ double g_d2[(size_t)NPTS * NPTS];      // 32 MB, fits in L2
__device__ double g_sq[NPTS];
__device__ double g_rowmin[NPTS];
__device__ int    g_rowarg[NPTS];
__device__ double g_sizes[NPTS];
__device__ int    g_active[NPTS];
__device__ int    g_cluster[NPTS];
__device__ int    g_labels[NPTS];

__device__ __forceinline__ double dinf() {
    return __longlong_as_double(0x7ff0000000000000LL);
}

// ---------------------------------------------------------------------------
// Init: squared norms + per-point state
// ---------------------------------------------------------------------------
__global__ void k_init_sq(const float* __restrict__ x) {
    int i = blockIdx.x * blockDim.x + threadIdx.x;
    if (i >= NPTS) return;
    const float* xr = x + (size_t)i * DIMS;
    double acc = 0.0;
    #pragma unroll 8
    for (int d = 0; d < DIMS; d++) {
        double v = (double)xr[d];
        acc = fma(v, v, acc);
    }
    g_sq[i] = acc;
    g_sizes[i] = 1.0;
    g_active[i] = 1;
    g_cluster[i] = i;
}

// ---------------------------------------------------------------------------
// Init: full fp64 squared-distance matrix  d2 = max(sq_i + sq_j - 2*dot, 0)
// blockIdx.y = i, threads cover j
// ---------------------------------------------------------------------------
__global__ void k_init_d2(const float* __restrict__ x) {
    __shared__ float xi[DIMS];
    int i = blockIdx.y;
    int j = blockIdx.x * blockDim.x + threadIdx.x;
    if (threadIdx.x < DIMS) xi[threadIdx.x] = x[(size_t)i * DIMS + threadIdx.x];
    __syncthreads();
    if (j >= NPTS) return;
    if (i == j) {
        g_d2[(size_t)i * NPTS + j] = dinf();
        return;
    }
    const float* xj = x + (size_t)j * DIMS;
    double dot = 0.0;
    #pragma unroll 8
    for (int d = 0; d < DIMS; d++) {
        dot = fma((double)xi[d], (double)xj[d], dot);
    }
    double v = g_sq[i] + g_sq[j] - 2.0 * dot;
    if (v < 0.0) v = 0.0;
    g_d2[(size_t)i * NPTS + j] = v;
}

// ---------------------------------------------------------------------------
// Init: per-row min + argmin (smallest-col tie-break). One block per row.
// ---------------------------------------------------------------------------
__global__ void k_init_rowmin() {
    __shared__ double sv[256];
    __shared__ int    sc[256];
    int r = blockIdx.x;
    int t = threadIdx.x;
    double bv = dinf();
    int bc = -1;
    const double* row = g_d2 + (size_t)r * NPTS;
    for (int c = t; c < NPTS; c += 256) {
        double v = row[c];
        if (v < bv) { bv = v; bc = c; }   // ascending c + strict < => smallest col on tie
    }
    sv[t] = bv; sc[t] = bc;
    __syncthreads();
    for (int s = 128; s > 0; s >>= 1) {
        if (t < s) {
            double v2 = sv[t + s]; int c2 = sc[t + s];
            if (v2 < sv[t] || (v2 == sv[t] && c2 >= 0 && (sc[t] < 0 || c2 < sc[t]))) {
                sv[t] = v2; sc[t] = c2;
            }
        }
        __syncthreads();
    }
    if (t == 0) { g_rowmin[r] = sv[0]; g_rowarg[r] = sc[0]; }
}

// ---------------------------------------------------------------------------
// Persistent Ward merge loop: single block, 1024 threads.
// ---------------------------------------------------------------------------
__global__ void __launch_bounds__(NTHREADS, 1)
k_ward(int K) {
    __shared__ double sVal[NTHREADS];
    __shared__ int    sRow[NTHREADS];
    __shared__ unsigned char sFlag[NPTS];
    __shared__ int    sList[NPTS];
    __shared__ int    sCnt;
    __shared__ int    s_i, s_j;
    __shared__ double s_dij, s_si, s_sj;

    const int t = threadIdx.x;
    const double INF = dinf();
    const int iters = NPTS - K;

    for (int it = 0; it < iters; ++it) {
        // ---- Phase A: global argmin over rowmin (numpy flat-argmin order) ----
        double bv = INF; int br = -1;
        for (int r = t; r < NPTS; r += NTHREADS) {
            double v = g_rowmin[r];
            if (v < bv) { bv = v; br = r; }   // strict <, ascending r
        }
        sVal[t] = bv; sRow[t] = br;
        __syncthreads();
        for (int s = NTHREADS / 2; s > 0; s >>= 1) {
            if (t < s) {
                double v2 = sVal[t + s]; int r2 = sRow[t + s];
                if (v2 < sVal[t] ||
                    (v2 == sVal[t] && r2 >= 0 && (sRow[t] < 0 || r2 < sRow[t]))) {
                    sVal[t] = v2; sRow[t] = r2;
                }
            }
            __syncthreads();
        }
        if (t == 0) {
            int i = sRow[0];
            int j = g_rowarg[i];
            if (i > j) { int tmp = i; i = j; j = tmp; }
            s_i = i; s_j = j;
            s_dij = g_d2[(size_t)i * NPTS + j];
            s_si = g_sizes[i]; s_sj = g_sizes[j];
            sCnt = 0;
        }
        __syncthreads();
        const int i = s_i, j = s_j;
        const double dij = s_dij, si = s_si, sj = s_sj;

        // ---- Phase C: Lance-Williams update of row/col i; kill j ----
        for (int m = t; m < NPTS; m += NTHREADS) {
            sFlag[m] = 0;
            if (g_active[m] && m != i && m != j) {
                double sm = g_sizes[m];
                double a = g_d2[(size_t)i * NPTS + m];
                double b = g_d2[(size_t)j * NPTS + m];
                // exact numpy expression order:
                double nd = ((si + sm) * a + (sj + sm) * b - sm * dij) / ((si + sj) + sm);
                g_d2[(size_t)i * NPTS + m] = nd;
                g_d2[(size_t)m * NPTS + i] = nd;
                int ra = g_rowarg[m];
                if (ra == i || ra == j) {
                    sFlag[m] = 1;                       // cached min invalidated -> rescan
                } else if (nd < g_rowmin[m] || (nd == g_rowmin[m] && i < ra)) {
                    g_rowmin[m] = nd; g_rowarg[m] = i;  // incremental improve
                }
            }
            if (g_cluster[m] == j) g_cluster[m] = i;
        }
        __syncthreads();
        if (t == 0) {
            g_sizes[i] = si + sj;
            g_active[j] = 0;
            g_rowmin[j] = INF;
            sFlag[i] = 1;       // row i fully changed
        }
        __syncthreads();

        // ---- build rescan list ----
        for (int m = t; m < NPTS; m += NTHREADS) {
            if (sFlag[m] && g_active[m]) {
                int p = atomicAdd(&sCnt, 1);
                sList[p] = m;
            }
        }
        __syncthreads();
        const int cnt = sCnt;

        // ---- Phase D: rescan flagged rows, one warp per row ----
        const int warp = t >> 5, lane = t & 31;
        for (int q = warp; q < cnt; q += (NTHREADS / 32)) {
            int r = sList[q];
            const double* row = g_d2 + (size_t)r * NPTS;
            double bv2 = INF; int bc = -1;
            for (int c = lane; c < NPTS; c += 32) {
                if (g_active[c] && c != r) {
                    double v = row[c];
                    if (v < bv2) { bv2 = v; bc = c; }
                }
            }
            #pragma unroll
            for (int o = 16; o > 0; o >>= 1) {
                double ov = __shfl_down_sync(0xffffffffu, bv2, o);
                int    oc = __shfl_down_sync(0xffffffffu, bc, o);
                if (ov < bv2 || (ov == bv2 && oc >= 0 && (bc < 0 || oc < bc))) {
                    bv2 = ov; bc = oc;
                }
            }
            if (lane == 0) { g_rowmin[r] = bv2; g_rowarg[r] = bc; }
        }
        __syncthreads();
    }
}

// ---------------------------------------------------------------------------
// Relabel: label = rank of surviving cluster id (== np.unique inverse)
// ---------------------------------------------------------------------------
__global__ void k_finalize() {
    int p = blockIdx.x * blockDim.x + threadIdx.x;
    if (p >= NPTS) return;
    int c = g_cluster[p];
    int rank = 0;
    for (int q = 0; q < c; q++) rank += g_active[q];
    g_labels[p] = rank;
}

__global__ void k_writeout(float* __restrict__ out, int K) {
    int idx = blockIdx.x * blockDim.x + threadIdx.x;
    int total = NPTS * K;
    if (idx >= total) return;
    int p = idx / K;
    int c = idx - p * K;
    out[idx] = (g_labels[p] == c) ? 1.0f : 0.0f;
}

// ---------------------------------------------------------------------------
extern "C" void kernel_launch(void* const* d_in, const int* in_sizes, int n_in,
                              void* d_out, int out_size) {
    const float* x = (const float*)d_in[0];
    int K = out_size / NPTS;   // out = [B*N, K] one-hot => K from out_size

    k_init_sq<<<(NPTS + 255) / 256, 256>>>(x);
    k_init_d2<<<dim3(NPTS / 128, NPTS), 128>>>(x);
    k_init_rowmin<<<NPTS, 256>>>();
    k_ward<<<1, NTHREADS>>>(K);
    k_finalize<<<(NPTS + 255) / 256, 256>>>();
    k_writeout<<<(NPTS * K + 255) / 256, 256>>>((float*)d_out, K);
}

// round 2
// speedup vs baseline: 1.5435x; 1.5435x over previous
#include <cuda_runtime.h>
#include <cuda_bf16.h>
#include <cstdint>

#define NPTS 2048
#define DIMS 96
#define NTHREADS 1024

// Device scratch (no runtime allocation allowed)
__device__ double g_d2[(size_t)NPTS * NPTS];      // 32 MB, L2-resident
__device__ double g_sq[NPTS];
__device__ double g_rowmin[NPTS];
__device__ int    g_rowarg[NPTS];
__device__ int    g_parent[NPTS];
__device__ int    g_active[NPTS];
__device__ int    g_labels[NPTS];

__device__ __forceinline__ double dinf() {
    return __longlong_as_double(0x7ff0000000000000LL);
}

// ---------------------------------------------------------------------------
// Init: squared norms
// ---------------------------------------------------------------------------
__global__ void k_init_sq(const float* __restrict__ x) {
    int i = blockIdx.x * blockDim.x + threadIdx.x;
    if (i >= NPTS) return;
    const float* xr = x + (size_t)i * DIMS;
    double acc = 0.0;
    #pragma unroll 8
    for (int d = 0; d < DIMS; d++) {
        double v = (double)xr[d];
        acc = fma(v, v, acc);
    }
    g_sq[i] = acc;
}

// ---------------------------------------------------------------------------
// Init: full fp64 squared-distance matrix  d2 = max(sq_i + sq_j - 2*dot, 0)
// ---------------------------------------------------------------------------
__global__ void k_init_d2(const float* __restrict__ x) {
    __shared__ float xi[DIMS];
    int i = blockIdx.y;
    int j = blockIdx.x * blockDim.x + threadIdx.x;
    if (threadIdx.x < DIMS) xi[threadIdx.x] = x[(size_t)i * DIMS + threadIdx.x];
    __syncthreads();
    if (j >= NPTS) return;
    if (i == j) {
        g_d2[(size_t)i * NPTS + j] = dinf();
        return;
    }
    const float* xj = x + (size_t)j * DIMS;
    double dot = 0.0;
    #pragma unroll 8
    for (int d = 0; d < DIMS; d++) {
        dot = fma((double)xi[d], (double)xj[d], dot);
    }
    double v = g_sq[i] + g_sq[j] - 2.0 * dot;
    if (v < 0.0) v = 0.0;
    g_d2[(size_t)i * NPTS + j] = v;
}

// ---------------------------------------------------------------------------
// Init: per-row min + argmin (smallest-col tie-break). One block per row.
// ---------------------------------------------------------------------------
__global__ void k_init_rowmin() {
    __shared__ double sv[256];
    __shared__ int    sc[256];
    int r = blockIdx.x;
    int t = threadIdx.x;
    double bv = dinf();
    int bc = NPTS;
    const double* row = g_d2 + (size_t)r * NPTS;
    for (int c = t; c < NPTS; c += 256) {
        double v = row[c];
        if (v < bv) { bv = v; bc = c; }   // ascending c + strict < => smallest col on tie
    }
    sv[t] = bv; sc[t] = bc;
    __syncthreads();
    for (int s = 128; s > 0; s >>= 1) {
        if (t < s) {
            double v2 = sv[t + s]; int c2 = sc[t + s];
            if (v2 < sv[t] || (v2 == sv[t] && c2 < sc[t])) {
                sv[t] = v2; sc[t] = c2;
            }
        }
        __syncthreads();
    }
    if (t == 0) { g_rowmin[r] = sv[0]; g_rowarg[r] = sc[0]; }
}

// ---------------------------------------------------------------------------
// Persistent Ward merge loop: single block, 1024 threads, state in SMEM.
// ---------------------------------------------------------------------------
__global__ void __launch_bounds__(NTHREADS, 1)
k_ward(int K) {
    __shared__ double s_rowmin[NPTS];          // 16 KB
    __shared__ short  s_rowarg[NPTS];          // 4 KB
    __shared__ unsigned short s_sizes[NPTS];   // 4 KB
    __shared__ unsigned char  s_active[NPTS];  // 2 KB
    __shared__ short  s_list[NPTS];            // 4 KB
    __shared__ double s_redv[32];
    __shared__ int    s_redr[32];
    __shared__ double s_pv[32];
    __shared__ int    s_pc[32];
    __shared__ int    s_cnt;
    __shared__ int    s_i, s_j;
    __shared__ double s_dij, s_si, s_sj;

    const int t = threadIdx.x;
    const int w = t >> 5, lane = t & 31;
    const double INF = dinf();

    // Load state into shared
    for (int r = t; r < NPTS; r += NTHREADS) {
        s_rowmin[r] = g_rowmin[r];
        s_rowarg[r] = (short)g_rowarg[r];
        s_sizes[r]  = 1;
        s_active[r] = 1;
    }
    __syncthreads();

    const int iters = NPTS - K;
    for (int it = 0; it < iters; ++it) {
        // ---- Phase A: global argmin over rowmin (flat-argmin tie order) ----
        double v0 = s_rowmin[t];
        double v1 = s_rowmin[t + NTHREADS];
        double bv; int br;
        if (v1 < v0) { bv = v1; br = t + NTHREADS; } else { bv = v0; br = t; }
        #pragma unroll
        for (int o = 16; o > 0; o >>= 1) {
            double ov = __shfl_down_sync(0xffffffffu, bv, o);
            int   orr = __shfl_down_sync(0xffffffffu, br, o);
            if (ov < bv || (ov == bv && orr < br)) { bv = ov; br = orr; }
        }
        if (lane == 0) { s_redv[w] = bv; s_redr[w] = br; }
        __syncthreads();
        if (w == 0) {
            double rv = s_redv[lane];
            int    rr = s_redr[lane];
            #pragma unroll
            for (int o = 16; o > 0; o >>= 1) {
                double ov = __shfl_down_sync(0xffffffffu, rv, o);
                int   orr = __shfl_down_sync(0xffffffffu, rr, o);
                if (ov < rv || (ov == rv && orr < rr)) { rv = ov; rr = orr; }
            }
            if (lane == 0) {
                int i = rr, j = (int)s_rowarg[rr];
                if (i > j) { int tmp = i; i = j; j = tmp; }
                s_i = i; s_j = j;
                s_dij = rv;                      // rowmin value == d2[i][j] bit-exact
                s_si = (double)s_sizes[i];
                s_sj = (double)s_sizes[j];
                s_cnt = 0;
            }
        }
        __syncthreads();
        const int i = s_i, j = s_j;
        const double dij = s_dij, si = s_si, sj = s_sj;

        // ---- Phase C: Lance-Williams update of row/col i (2 elems/thread) ----
        {
            const int m0 = t, m1 = t + NTHREADS;
            const bool p0 = s_active[m0] && m0 != i && m0 != j;
            const bool p1 = s_active[m1] && m1 != i && m1 != j;
            double a0 = 0.0, b0 = 0.0, a1 = 0.0, b1 = 0.0;
            if (p0) { a0 = g_d2[(size_t)i * NPTS + m0]; b0 = g_d2[(size_t)j * NPTS + m0]; }
            if (p1) { a1 = g_d2[(size_t)i * NPTS + m1]; b1 = g_d2[(size_t)j * NPTS + m1]; }
            if (p0) {
                double sm = (double)s_sizes[m0];
                double nd = ((si + sm) * a0 + (sj + sm) * b0 - sm * dij) / (si + sj + sm);
                g_d2[(size_t)i * NPTS + m0] = nd;
                g_d2[(size_t)m0 * NPTS + i] = nd;
                short ra = s_rowarg[m0];
                if (ra == i || ra == j) {
                    int p = atomicAdd(&s_cnt, 1); s_list[p] = (short)m0;
                } else if (nd < s_rowmin[m0] || (nd == s_rowmin[m0] && i < ra)) {
                    s_rowmin[m0] = nd; s_rowarg[m0] = (short)i;
                }
            }
            if (p1) {
                double sm = (double)s_sizes[m1];
                double nd = ((si + sm) * a1 + (sj + sm) * b1 - sm * dij) / (si + sj + sm);
                g_d2[(size_t)i * NPTS + m1] = nd;
                g_d2[(size_t)m1 * NPTS + i] = nd;
                short ra = s_rowarg[m1];
                if (ra == i || ra == j) {
                    int p = atomicAdd(&s_cnt, 1); s_list[p] = (short)m1;
                } else if (nd < s_rowmin[m1] || (nd == s_rowmin[m1] && i < ra)) {
                    s_rowmin[m1] = nd; s_rowarg[m1] = (short)i;
                }
            }
        }
        if (t == 0) {
            s_sizes[i]  = (unsigned short)(s_sizes[i] + s_sizes[j]);
            s_active[j] = 0;
            s_rowmin[j] = INF;
            g_parent[j] = i;
            int p = atomicAdd(&s_cnt, 1); s_list[p] = (short)i;  // row i always rescanned
        }
        __syncthreads();
        const int cnt = s_cnt;

        // ---- Phase D: rescan flagged rows; split each row across S warps ----
        int S;
        if (cnt >= 32) S = 1;
        else { int qq = 32 / cnt; S = 1; while ((S << 1) <= qq) S <<= 1; }
        const int segLen = NPTS / S;

        for (int base = 0; base < cnt * S; base += 32) {
            int task = base + w;
            if (task < cnt * S) {
                int q = task / S, seg = task - q * S;
                int r = (int)s_list[q];
                const double* row = g_d2 + (size_t)r * NPTS;
                double bv2 = INF; int bc = NPTS;
                int c0 = seg * segLen;
                for (int c = c0 + lane; c < c0 + segLen; c += 32) {
                    if (s_active[c]) {
                        double v = row[c];
                        if (v < bv2) { bv2 = v; bc = c; }
                    }
                }
                #pragma unroll
                for (int o = 16; o > 0; o >>= 1) {
                    double ov = __shfl_down_sync(0xffffffffu, bv2, o);
                    int    oc = __shfl_down_sync(0xffffffffu, bc, o);
                    if (ov < bv2 || (ov == bv2 && oc < bc)) { bv2 = ov; bc = oc; }
                }
                if (lane == 0) {
                    if (S == 1) { s_rowmin[r] = bv2; s_rowarg[r] = (short)bc; }
                    else        { s_pv[task] = bv2; s_pc[task] = bc; }
                }
            }
        }
        if (S > 1) {
            __syncthreads();
            if (w < cnt) {
                double rv = (lane < S) ? s_pv[w * S + lane] : INF;
                int    rc = (lane < S) ? s_pc[w * S + lane] : NPTS;
                #pragma unroll
                for (int o = 16; o > 0; o >>= 1) {
                    double ov = __shfl_down_sync(0xffffffffu, rv, o);
                    int    oc = __shfl_down_sync(0xffffffffu, rc, o);
                    if (ov < rv || (ov == rv && oc < rc)) { rv = ov; rc = oc; }
                }
                if (lane == 0) {
                    int r = (int)s_list[w];
                    s_rowmin[r] = rv; s_rowarg[r] = (short)rc;
                }
            }
        }
        __syncthreads();
    }

    // Write back active flags for finalize
    for (int r = t; r < NPTS; r += NTHREADS) g_active[r] = (int)s_active[r];
}

// ---------------------------------------------------------------------------
// Relabel: follow parent chain to active representative; label = rank among
// sorted surviving cluster ids (== np.unique inverse).
// ---------------------------------------------------------------------------
__global__ void k_finalize() {
    int p = blockIdx.x * blockDim.x + threadIdx.x;
    if (p >= NPTS) return;
    int c = p;
    while (!g_active[c]) c = g_parent[c];
    int rank = 0;
    for (int q = 0; q < c; q++) rank += g_active[q];
    g_labels[p] = rank;
}

__global__ void k_writeout(float* __restrict__ out, int K) {
    int idx = blockIdx.x * blockDim.x + threadIdx.x;
    int total = NPTS * K;
    if (idx >= total) return;
    int p = idx / K;
    int c = idx - p * K;
    out[idx] = (g_labels[p] == c) ? 1.0f : 0.0f;
}

// ---------------------------------------------------------------------------
extern "C" void kernel_launch(void* const* d_in, const int* in_sizes, int n_in,
                              void* d_out, int out_size) {
    const float* x = (const float*)d_in[0];
    int K = out_size / NPTS;   // out = [B*N, K] one-hot => K from out_size

    k_init_sq<<<(NPTS + 255) / 256, 256>>>(x);
    k_init_d2<<<dim3(NPTS / 128, NPTS), 128>>>(x);
    k_init_rowmin<<<NPTS, 256>>>();
    k_ward<<<1, NTHREADS>>>(K);
    k_finalize<<<(NPTS + 255) / 256, 256>>>();
    k_writeout<<<(NPTS * K + 255) / 256, 256>>>((float*)d_out, K);
}